// round 9
// baseline (speedup 1.0000x reference)
#include <cuda_runtime.h>
#include <cuda_fp16.h>

#define HH 256
#define WW 256
#define KK 64
#define MV 16
#define NSTEPS 64
#define VOLR 256.0f
#define DTST (1.0f/256.0f)

// Template with paired x-cells: entry [k][z][y][x] holds {cell(x), cell(x+1)} as
// uint4 { half2(r,g)@x, half2(b,a)@x, half2(r,g)@x+1, half2(b,a)@x+1 } : 4 MB
__device__ uint4 g_tmpl[KK * MV * MV * MV];
// Per-prim params as 4 float4 per prim:
//  A = {R00,R01,R02,R10}, B = {R11,R12,R20,R21}, C = {R22,px,py,pz}, D = {sx,sy,sz,0}
__device__ float4 g_prim[KK * 4];

// Blocks 0..1023: repack template to paired fp16. Block 1024: prep prim params.
__global__ void pack_prep_kernel(const float* __restrict__ primrgba,
                                 const float* __restrict__ primpos,
                                 const float* __restrict__ primrot,
                                 const float* __restrict__ primscale) {
    int b = blockIdx.x;
    if (b < 1024) {
        int idx = b * 256 + threadIdx.x;
        int k = idx >> 12;
        int v = idx & 4095;          // z*256 + y*16 + x
        int x = v & 15;
        int v1 = (x < 15) ? v + 1 : v;  // clamp (x=15 entry never read with x1 offset)
        const float* base = primrgba + (size_t)k * 4 * 4096;
        __half2 rg0 = __floats2half2_rn(base[v], base[4096 + v]);
        __half2 ba0 = __floats2half2_rn(base[8192 + v], base[12288 + v]);
        __half2 rg1 = __floats2half2_rn(base[v1], base[4096 + v1]);
        __half2 ba1 = __floats2half2_rn(base[8192 + v1], base[12288 + v1]);
        uint4 val;
        val.x = *reinterpret_cast<unsigned*>(&rg0);
        val.y = *reinterpret_cast<unsigned*>(&ba0);
        val.z = *reinterpret_cast<unsigned*>(&rg1);
        val.w = *reinterpret_cast<unsigned*>(&ba1);
        g_tmpl[idx] = val;
    } else {
        int k = threadIdx.x;
        if (k >= KK) return;
        float R[9];
#pragma unroll
        for (int i = 0; i < 9; i++) R[i] = primrot[k * 9 + i];
        float4 A = {R[0], R[1], R[2], R[3]};
        float4 Bv = {R[4], R[5], R[6], R[7]};
        float4 Cv = {R[8],
                     primpos[k * 3 + 0] / VOLR,
                     primpos[k * 3 + 1] / VOLR,
                     primpos[k * 3 + 2] / VOLR};
        float4 Dv = {primscale[k * 3 + 0],
                     primscale[k * 3 + 1],
                     primscale[k * 3 + 2], 0.f};
        g_prim[k * 4 + 0] = A;
        g_prim[k * 4 + 1] = Bv;
        g_prim[k * 4 + 2] = Cv;
        g_prim[k * 4 + 3] = Dv;
    }
}

// Full per-point evaluation: transform + inside test + paired fp16 trilinear gather.
__device__ __forceinline__ void eval_prim(
    const float4 A, const float4 B, const float4 C, const float4 D, int k,
    float px, float py, float pz, float s[4])
{
    float rx = px - C.y, ry = py - C.z, rz = pz - C.w;
    float lx = (rx * A.x + ry * A.w + rz * B.z) * D.x;
    float ly = (rx * A.y + ry * B.x + rz * B.w) * D.y;
    float lz = (rx * A.z + ry * B.y + rz * C.x) * D.z;
    if (!(fabsf(lx) < 1.0f && fabsf(ly) < 1.0f && fabsf(lz) < 1.0f)) return;

    float gx = fminf((lx + 1.0f) * 7.5f, 14.99999f);
    float gy = fminf((ly + 1.0f) * 7.5f, 14.99999f);
    float gz = fminf((lz + 1.0f) * 7.5f, 14.99999f);
    int x0 = (int)gx;
    int y0 = (int)gy;
    int z0 = (int)gz;
    float fx = gx - (float)x0;
    float fy = gy - (float)y0;
    float fz = gz - (float)z0;

    // 4 aligned LDG.128: each holds corners (x0, x0+1) for one (z,y)
    const uint4* T = g_tmpl + (((k * MV + z0) * MV + y0) * MV + x0);
    uint4 q00 = __ldg(T + 0);    // z0,   y0
    uint4 q01 = __ldg(T + 16);   // z0,   y0+1
    uint4 q10 = __ldg(T + 256);  // z0+1, y0
    uint4 q11 = __ldg(T + 272);  // z0+1, y0+1

    float wz0 = 1.0f - fz, wy0 = 1.0f - fy, wx0 = 1.0f - fx;
    float w000 = wz0 * wy0 * wx0, w001 = wz0 * wy0 * fx;
    float w010 = wz0 * fy * wx0,  w011 = wz0 * fy * fx;
    float w100 = fz * wy0 * wx0,  w101 = fz * wy0 * fx;
    float w110 = fz * fy * wx0,   w111 = fz * fy * fx;

#define ACC2(q, wA, wB)                                                   \
    {                                                                     \
        float2 rgA = __half22float2(*reinterpret_cast<const __half2*>(&(q).x)); \
        float2 baA = __half22float2(*reinterpret_cast<const __half2*>(&(q).y)); \
        float2 rgB = __half22float2(*reinterpret_cast<const __half2*>(&(q).z)); \
        float2 baB = __half22float2(*reinterpret_cast<const __half2*>(&(q).w)); \
        s[0] = fmaf(rgA.x, (wA), s[0]); s[1] = fmaf(rgA.y, (wA), s[1]);   \
        s[2] = fmaf(baA.x, (wA), s[2]); s[3] = fmaf(baA.y, (wA), s[3]);   \
        s[0] = fmaf(rgB.x, (wB), s[0]); s[1] = fmaf(rgB.y, (wB), s[1]);   \
        s[2] = fmaf(baB.x, (wB), s[2]); s[3] = fmaf(baB.y, (wB), s[3]);   \
    }
    ACC2(q00, w000, w001)
    ACC2(q01, w010, w011)
    ACC2(q10, w100, w101)
    ACC2(q11, w110, w111)
#undef ACC2
}

// Exact OBB slab test (cull only).
__device__ __forceinline__ bool obb_test(
    const float4* __restrict__ sP4, int k,
    float ox, float oy, float oz,
    float dx, float dy, float dz,
    float tmin, float tmax)
{
    float4 A = sP4[k * 4 + 0];
    float4 B = sP4[k * 4 + 1];
    float4 C = sP4[k * 4 + 2];
    float4 D = sP4[k * 4 + 3];
    float rx = ox - C.y, ry = oy - C.z, rz = oz - C.w;
    float lo3[3], ld3[3];
    lo3[0] = (rx * A.x + ry * A.w + rz * B.z) * D.x;
    lo3[1] = (rx * A.y + ry * B.x + rz * B.w) * D.y;
    lo3[2] = (rx * A.z + ry * B.y + rz * C.x) * D.z;
    ld3[0] = (dx * A.x + dy * A.w + dz * B.z) * D.x;
    ld3[1] = (dx * A.y + dy * B.x + dz * B.w) * D.y;
    ld3[2] = (dx * A.z + dy * B.y + dz * C.x) * D.z;
    float t0 = tmin, t1 = tmax;
#pragma unroll
    for (int a = 0; a < 3; a++) {
        float lo = lo3[a], ld = ld3[a];
        if (fabsf(ld) > 1e-12f) {
            float inv = 1.0f / ld;
            float ta = (-1.0f - lo) * inv;
            float tb = ( 1.0f - lo) * inv;
            t0 = fmaxf(t0, fminf(ta, tb));
            t1 = fminf(t1, fmaxf(ta, tb));
        } else if (fabsf(lo) >= 1.0f) {
            return false;
        }
    }
    return t0 <= t1;
}

// 2 warps per ray (warp half h owns steps h*32+lane); 4 consecutive rays per block.
// Rows bit-reversed across blockIdx so hot central rows launch early (tail balancing).
__global__ __launch_bounds__(256) void march_kernel(
    const float* __restrict__ raypos,
    const float* __restrict__ raydir,
    const float* __restrict__ tminmax,
    float* __restrict__ out)
{
    __shared__ float4 sP4[KK * 4];
    __shared__ float sTot[4];     // half0's d-sum per ray
    __shared__ float4 sPart[4];   // half0's rgb partial per ray
    for (int i = threadIdx.x; i < KK * 4; i += 256) sP4[i] = g_prim[i];
    __syncthreads();

    int lane = threadIdx.x & 31;
    int warpId = threadIdx.x >> 5;   // 0..7
    int rayIn = warpId >> 1;         // 0..3
    int half = warpId & 1;           // 0: steps 0-31, 1: steps 32-63

    int b = blockIdx.x;
    int row = (int)(__brev((unsigned)(b >> 6)) >> 24);  // bit-reversed row
    int col4 = b & 63;
    int r = row * WW + col4 * 4 + rayIn;

    float ox = raypos[r * 3 + 0], oy = raypos[r * 3 + 1], oz = raypos[r * 3 + 2];
    float dx = raydir[r * 3 + 0], dy = raydir[r * 3 + 1], dz = raydir[r * 3 + 2];
    float tmin = tminmax[r * 2 + 0], tmax = tminmax[r * 2 + 1];

    // Cooperative exact-OBB cull: lane tests prims {lane, lane+32}
    bool a0 = obb_test(sP4, lane,      ox, oy, oz, dx, dy, dz, tmin, tmax);
    bool a1 = obb_test(sP4, lane + 32, ox, oy, oz, dx, dy, dz, tmin, tmax);
    unsigned m0 = __ballot_sync(0xFFFFFFFFu, a0);
    unsigned m1 = __ballot_sync(0xFFFFFFFFu, a1);
    unsigned long long mask = (unsigned long long)m0 |
                              ((unsigned long long)m1 << 32);

    // One sample point per lane
    int step = half * 32 + lane;
    float t = fmaf((float)step + 0.5f, DTST, tmin);
    float px = fmaf(t, dx, ox), py = fmaf(t, dy, oy), pz = fmaf(t, dz, oz);

    float s[4] = {0.f, 0.f, 0.f, 0.f};

    while (mask) {
        int k = __ffsll(mask) - 1;   // warp-uniform
        mask &= mask - 1;
        float4 A = sP4[k * 4 + 0];   // LDS.128 broadcast x4
        float4 B = sP4[k * 4 + 1];
        float4 C = sP4[k * 4 + 2];
        float4 D = sP4[k * 4 + 3];
        eval_prim(A, B, C, D, k, px, py, pz, s);
    }

    // Alpha compositing: alpha_i = min(1, prefix sum of d)
    float d = (t < tmax) ? s[3] * DTST : 0.f;
    float c = d;
#pragma unroll
    for (int off = 1; off < 32; off <<= 1) {
        float v = __shfl_up_sync(0xFFFFFFFFu, c, off);
        if (lane >= off) c += v;
    }
    float tot = __shfl_sync(0xFFFFFFFFu, c, 31);
    if (half == 0 && lane == 0) sTot[rayIn] = tot;
    __syncthreads();

    float S = half ? (sTot[rayIn] + c) : c;   // global inclusive prefix at this step
    float contrib = fminf(1.f, S) - fminf(1.f, S - d);

    float rgbx = s[0] * contrib;
    float rgby = s[1] * contrib;
    float rgbz = s[2] * contrib;
#pragma unroll
    for (int off = 16; off > 0; off >>= 1) {
        rgbx += __shfl_xor_sync(0xFFFFFFFFu, rgbx, off);
        rgby += __shfl_xor_sync(0xFFFFFFFFu, rgby, off);
        rgbz += __shfl_xor_sync(0xFFFFFFFFu, rgbz, off);
    }

    if (half == 0 && lane == 0) {
        sPart[rayIn] = make_float4(rgbx, rgby, rgbz, 0.f);
    }
    __syncthreads();

    if (half == 1 && lane == 0) {
        float4 p = sPart[rayIn];
        float ox2 = p.x + rgbx;
        float oy2 = p.y + rgby;
        float oz2 = p.z + rgbz;
        float alphaF = fminf(1.f, sTot[rayIn] + tot);
        const int HWsz = HH * WW;
        out[0 * HWsz + r] = ox2;
        out[1 * HWsz + r] = oy2;
        out[2 * HWsz + r] = oz2;
        out[3 * HWsz + r] = alphaF;
        out[4 * HWsz + r] = ox2;
        out[5 * HWsz + r] = oy2;
        out[6 * HWsz + r] = oz2;
        out[7 * HWsz + r] = alphaF;
    }
}

extern "C" void kernel_launch(void* const* d_in, const int* in_sizes, int n_in,
                              void* d_out, int out_size) {
    const float* raypos    = (const float*)d_in[0];
    const float* raydir    = (const float*)d_in[1];
    const float* tminmax   = (const float*)d_in[2];
    const float* primpos   = (const float*)d_in[3];
    const float* primrot   = (const float*)d_in[4];
    const float* primscale = (const float*)d_in[5];
    const float* primrgba  = (const float*)d_in[6];
    float* out = (float*)d_out;

    pack_prep_kernel<<<1025, 256>>>(primrgba, primpos, primrot, primscale);
    march_kernel<<<HH * WW / 4, 256>>>(raypos, raydir, tminmax, out);
}

// round 10
// speedup vs baseline: 1.5557x; 1.5557x over previous
#include <cuda_runtime.h>
#include <cuda_fp16.h>

#define HH 256
#define WW 256
#define KK 64
#define MV 16
#define NSTEPS 64
#define VOLR 256.0f
#define DTST (1.0f/256.0f)

// Template with paired x-cells: entry [k][z][y][x] holds {cell(x), cell(x+1)} as
// uint4 { half2(r,g)@x, half2(b,a)@x, half2(r,g)@x+1, half2(b,a)@x+1 } : 4 MB
__device__ uint4 g_tmpl[KK * MV * MV * MV];
// Per-prim params as 4 float4 per prim:
//  A = {R00,R01,R02,R10}, B = {R11,R12,R20,R21}, C = {R22,px,py,pz}, D = {sx,sy,sz,0}
__device__ float4 g_prim[KK * 4];

// Blocks 0..1023: repack template to paired fp16. Block 1024: prep prim params.
__global__ void pack_prep_kernel(const float* __restrict__ primrgba,
                                 const float* __restrict__ primpos,
                                 const float* __restrict__ primrot,
                                 const float* __restrict__ primscale) {
    int b = blockIdx.x;
    if (b < 1024) {
        int idx = b * 256 + threadIdx.x;
        int k = idx >> 12;
        int v = idx & 4095;          // z*256 + y*16 + x
        int x = v & 15;
        int v1 = (x < 15) ? v + 1 : v;  // clamp (x=15 entry never read with x1 offset)
        const float* base = primrgba + (size_t)k * 4 * 4096;
        __half2 rg0 = __floats2half2_rn(base[v], base[4096 + v]);
        __half2 ba0 = __floats2half2_rn(base[8192 + v], base[12288 + v]);
        __half2 rg1 = __floats2half2_rn(base[v1], base[4096 + v1]);
        __half2 ba1 = __floats2half2_rn(base[8192 + v1], base[12288 + v1]);
        uint4 val;
        val.x = *reinterpret_cast<unsigned*>(&rg0);
        val.y = *reinterpret_cast<unsigned*>(&ba0);
        val.z = *reinterpret_cast<unsigned*>(&rg1);
        val.w = *reinterpret_cast<unsigned*>(&ba1);
        g_tmpl[idx] = val;
    } else {
        int k = threadIdx.x;
        if (k >= KK) return;
        float R[9];
#pragma unroll
        for (int i = 0; i < 9; i++) R[i] = primrot[k * 9 + i];
        float4 A = {R[0], R[1], R[2], R[3]};
        float4 Bv = {R[4], R[5], R[6], R[7]};
        float4 Cv = {R[8],
                     primpos[k * 3 + 0] / VOLR,
                     primpos[k * 3 + 1] / VOLR,
                     primpos[k * 3 + 2] / VOLR};
        float4 Dv = {primscale[k * 3 + 0],
                     primscale[k * 3 + 1],
                     primscale[k * 3 + 2], 0.f};
        g_prim[k * 4 + 0] = A;
        g_prim[k * 4 + 1] = Bv;
        g_prim[k * 4 + 2] = Cv;
        g_prim[k * 4 + 3] = Dv;
    }
}

// Full per-point evaluation: transform + inside test + paired fp16 trilinear gather.
__device__ __forceinline__ void eval_prim(
    const float4 A, const float4 B, const float4 C, const float4 D, int k,
    float px, float py, float pz, float s[4])
{
    float rx = px - C.y, ry = py - C.z, rz = pz - C.w;
    float lx = (rx * A.x + ry * A.w + rz * B.z) * D.x;
    float ly = (rx * A.y + ry * B.x + rz * B.w) * D.y;
    float lz = (rx * A.z + ry * B.y + rz * C.x) * D.z;
    if (!(fabsf(lx) < 1.0f && fabsf(ly) < 1.0f && fabsf(lz) < 1.0f)) return;

    float gx = fminf((lx + 1.0f) * 7.5f, 14.99999f);
    float gy = fminf((ly + 1.0f) * 7.5f, 14.99999f);
    float gz = fminf((lz + 1.0f) * 7.5f, 14.99999f);
    int x0 = (int)gx;
    int y0 = (int)gy;
    int z0 = (int)gz;
    float fx = gx - (float)x0;
    float fy = gy - (float)y0;
    float fz = gz - (float)z0;

    // 4 aligned LDG.128: each holds corners (x0, x0+1) for one (z,y)
    const uint4* T = g_tmpl + (((k * MV + z0) * MV + y0) * MV + x0);
    uint4 q00 = __ldg(T + 0);    // z0,   y0
    uint4 q01 = __ldg(T + 16);   // z0,   y0+1
    uint4 q10 = __ldg(T + 256);  // z0+1, y0
    uint4 q11 = __ldg(T + 272);  // z0+1, y0+1

    float wz0 = 1.0f - fz, wy0 = 1.0f - fy, wx0 = 1.0f - fx;
    float w000 = wz0 * wy0 * wx0, w001 = wz0 * wy0 * fx;
    float w010 = wz0 * fy * wx0,  w011 = wz0 * fy * fx;
    float w100 = fz * wy0 * wx0,  w101 = fz * wy0 * fx;
    float w110 = fz * fy * wx0,   w111 = fz * fy * fx;

#define ACC2(q, wA, wB)                                                   \
    {                                                                     \
        float2 rgA = __half22float2(*reinterpret_cast<const __half2*>(&(q).x)); \
        float2 baA = __half22float2(*reinterpret_cast<const __half2*>(&(q).y)); \
        float2 rgB = __half22float2(*reinterpret_cast<const __half2*>(&(q).z)); \
        float2 baB = __half22float2(*reinterpret_cast<const __half2*>(&(q).w)); \
        s[0] = fmaf(rgA.x, (wA), s[0]); s[1] = fmaf(rgA.y, (wA), s[1]);   \
        s[2] = fmaf(baA.x, (wA), s[2]); s[3] = fmaf(baA.y, (wA), s[3]);   \
        s[0] = fmaf(rgB.x, (wB), s[0]); s[1] = fmaf(rgB.y, (wB), s[1]);   \
        s[2] = fmaf(baB.x, (wB), s[2]); s[3] = fmaf(baB.y, (wB), s[3]);   \
    }
    ACC2(q00, w000, w001)
    ACC2(q01, w010, w011)
    ACC2(q10, w100, w101)
    ACC2(q11, w110, w111)
#undef ACC2
}

// Exact OBB slab test (cull only).
__device__ __forceinline__ bool obb_test(
    const float4* __restrict__ sP4, int k,
    float ox, float oy, float oz,
    float dx, float dy, float dz,
    float tmin, float tmax)
{
    float4 A = sP4[k * 4 + 0];
    float4 B = sP4[k * 4 + 1];
    float4 C = sP4[k * 4 + 2];
    float4 D = sP4[k * 4 + 3];
    float rx = ox - C.y, ry = oy - C.z, rz = oz - C.w;
    float lo3[3], ld3[3];
    lo3[0] = (rx * A.x + ry * A.w + rz * B.z) * D.x;
    lo3[1] = (rx * A.y + ry * B.x + rz * B.w) * D.y;
    lo3[2] = (rx * A.z + ry * B.y + rz * C.x) * D.z;
    ld3[0] = (dx * A.x + dy * A.w + dz * B.z) * D.x;
    ld3[1] = (dx * A.y + dy * B.x + dz * B.w) * D.y;
    ld3[2] = (dx * A.z + dy * B.y + dz * C.x) * D.z;
    float t0 = tmin, t1 = tmax;
#pragma unroll
    for (int a = 0; a < 3; a++) {
        float lo = lo3[a], ld = ld3[a];
        if (fabsf(ld) > 1e-12f) {
            float inv = 1.0f / ld;
            float ta = (-1.0f - lo) * inv;
            float tb = ( 1.0f - lo) * inv;
            t0 = fmaxf(t0, fminf(ta, tb));
            t1 = fminf(t1, fmaxf(ta, tb));
        } else if (fabsf(lo) >= 1.0f) {
            return false;
        }
    }
    return t0 <= t1;
}

// One warp per ray; lane owns ADJACENT steps {2*lane, 2*lane+1} (cache-line sharing).
// 4 consecutive rays per 128-thread block (finer packing + shorter tail).
__global__ __launch_bounds__(128) void march_kernel(
    const float* __restrict__ raypos,
    const float* __restrict__ raydir,
    const float* __restrict__ tminmax,
    float* __restrict__ out)
{
    __shared__ float4 sP4[KK * 4];
    for (int i = threadIdx.x; i < KK * 4; i += 128) sP4[i] = g_prim[i];
    __syncthreads();

    int lane = threadIdx.x & 31;
    int warpId = threadIdx.x >> 5;
    int r = blockIdx.x * 4 + warpId;  // consecutive rays (L1 template locality)

    float ox = raypos[r * 3 + 0], oy = raypos[r * 3 + 1], oz = raypos[r * 3 + 2];
    float dx = raydir[r * 3 + 0], dy = raydir[r * 3 + 1], dz = raydir[r * 3 + 2];
    float tmin = tminmax[r * 2 + 0], tmax = tminmax[r * 2 + 1];

    // Cooperative exact-OBB cull: lane tests prims {lane, lane+32}
    bool a0 = obb_test(sP4, lane,      ox, oy, oz, dx, dy, dz, tmin, tmax);
    bool a1 = obb_test(sP4, lane + 32, ox, oy, oz, dx, dy, dz, tmin, tmax);
    unsigned m0 = __ballot_sync(0xFFFFFFFFu, a0);
    unsigned m1 = __ballot_sync(0xFFFFFFFFu, a1);
    unsigned long long mask = (unsigned long long)m0 |
                              ((unsigned long long)m1 << 32);

    // Two ADJACENT sample points per lane: steps 2*lane and 2*lane+1
    float t0 = fmaf(2.0f * (float)lane + 0.5f, DTST, tmin);
    float t1 = fmaf(2.0f * (float)lane + 1.5f, DTST, tmin);
    float p0x = fmaf(t0, dx, ox), p0y = fmaf(t0, dy, oy), p0z = fmaf(t0, dz, oz);
    float p1x = fmaf(t1, dx, ox), p1y = fmaf(t1, dy, oy), p1z = fmaf(t1, dz, oz);

    float s0[4] = {0.f, 0.f, 0.f, 0.f};
    float s1[4] = {0.f, 0.f, 0.f, 0.f};

    while (mask) {
        int k = __ffsll(mask) - 1;   // warp-uniform
        mask &= mask - 1;
        float4 A = sP4[k * 4 + 0];   // LDS.128 broadcast x4
        float4 B = sP4[k * 4 + 1];
        float4 C = sP4[k * 4 + 2];
        float4 D = sP4[k * 4 + 3];
        eval_prim(A, B, C, D, k, p0x, p0y, p0z, s0);
        eval_prim(A, B, C, D, k, p1x, p1y, p1z, s1);
    }

    // Alpha compositing via prefix sum over adjacent pairs.
    float d0 = (t0 < tmax) ? s0[3] * DTST : 0.f;
    float d1 = (t1 < tmax) ? s1[3] * DTST : 0.f;
    float pairSum = d0 + d1;

    float c = pairSum;
#pragma unroll
    for (int off = 1; off < 32; off <<= 1) {
        float v = __shfl_up_sync(0xFFFFFFFFu, c, off);
        if (lane >= off) c += v;
    }
    // c = inclusive prefix of pair sums through this lane
    float S1 = c;            // inclusive prefix at odd step (2*lane+1)
    float S0 = c - d1;       // inclusive prefix at even step (2*lane)
    float contrib0 = fminf(1.f, S0) - fminf(1.f, S0 - d0);
    float contrib1 = fminf(1.f, S1) - fminf(1.f, S1 - d1);

    float rgbx = s0[0] * contrib0 + s1[0] * contrib1;
    float rgby = s0[1] * contrib0 + s1[1] * contrib1;
    float rgbz = s0[2] * contrib0 + s1[2] * contrib1;

#pragma unroll
    for (int off = 16; off > 0; off >>= 1) {
        rgbx += __shfl_xor_sync(0xFFFFFFFFu, rgbx, off);
        rgby += __shfl_xor_sync(0xFFFFFFFFu, rgby, off);
        rgbz += __shfl_xor_sync(0xFFFFFFFFu, rgbz, off);
    }
    float alphaF = fminf(1.f, __shfl_sync(0xFFFFFFFFu, S1, 31));

    if (lane == 0) {
        const int HWsz = HH * WW;
        out[0 * HWsz + r] = rgbx;
        out[1 * HWsz + r] = rgby;
        out[2 * HWsz + r] = rgbz;
        out[3 * HWsz + r] = alphaF;
        out[4 * HWsz + r] = rgbx;
        out[5 * HWsz + r] = rgby;
        out[6 * HWsz + r] = rgbz;
        out[7 * HWsz + r] = alphaF;
    }
}

extern "C" void kernel_launch(void* const* d_in, const int* in_sizes, int n_in,
                              void* d_out, int out_size) {
    const float* raypos    = (const float*)d_in[0];
    const float* raydir    = (const float*)d_in[1];
    const float* tminmax   = (const float*)d_in[2];
    const float* primpos   = (const float*)d_in[3];
    const float* primrot   = (const float*)d_in[4];
    const float* primscale = (const float*)d_in[5];
    const float* primrgba  = (const float*)d_in[6];
    float* out = (float*)d_out;

    pack_prep_kernel<<<1025, 256>>>(primrgba, primpos, primrot, primscale);
    march_kernel<<<HH * WW / 4, 128>>>(raypos, raydir, tminmax, out);
}

// round 11
// speedup vs baseline: 1.6398x; 1.0541x over previous
#include <cuda_runtime.h>
#include <cuda_fp16.h>

#define HH 256
#define WW 256
#define KK 64
#define MV 16
#define NSTEPS 64
#define VOLR 256.0f
#define DTST (1.0f/256.0f)

// Template with paired x-cells: entry [k][z][y][x] holds {cell(x), cell(x+1)} as
// uint4 { half2(r,g)@x, half2(b,a)@x, half2(r,g)@x+1, half2(b,a)@x+1 } : 4 MB
__device__ uint4 g_tmpl[KK * MV * MV * MV];
// Per-prim params as 4 float4 per prim:
//  A = {R00,R01,R02,R10}, B = {R11,R12,R20,R21}, C = {R22,px,py,pz}, D = {sx,sy,sz,0}
__device__ float4 g_prim[KK * 4];
// Constant-memory mirror (filled by D2D memcpy each launch) — inner loop reads
// it with a warp-uniform index -> LDC on the constant port, off the L1 pipe.
__constant__ float4 c_prim[KK * 4];

// Blocks 0..1023: repack template to paired fp16. Block 1024: prep prim params.
__global__ void pack_prep_kernel(const float* __restrict__ primrgba,
                                 const float* __restrict__ primpos,
                                 const float* __restrict__ primrot,
                                 const float* __restrict__ primscale) {
    int b = blockIdx.x;
    if (b < 1024) {
        int idx = b * 256 + threadIdx.x;
        int k = idx >> 12;
        int v = idx & 4095;          // z*256 + y*16 + x
        int x = v & 15;
        int v1 = (x < 15) ? v + 1 : v;  // clamp (x=15 entry never read with x1 offset)
        const float* base = primrgba + (size_t)k * 4 * 4096;
        __half2 rg0 = __floats2half2_rn(base[v], base[4096 + v]);
        __half2 ba0 = __floats2half2_rn(base[8192 + v], base[12288 + v]);
        __half2 rg1 = __floats2half2_rn(base[v1], base[4096 + v1]);
        __half2 ba1 = __floats2half2_rn(base[8192 + v1], base[12288 + v1]);
        uint4 val;
        val.x = *reinterpret_cast<unsigned*>(&rg0);
        val.y = *reinterpret_cast<unsigned*>(&ba0);
        val.z = *reinterpret_cast<unsigned*>(&rg1);
        val.w = *reinterpret_cast<unsigned*>(&ba1);
        g_tmpl[idx] = val;
    } else {
        int k = threadIdx.x;
        if (k >= KK) return;
        float R[9];
#pragma unroll
        for (int i = 0; i < 9; i++) R[i] = primrot[k * 9 + i];
        float4 A = {R[0], R[1], R[2], R[3]};
        float4 Bv = {R[4], R[5], R[6], R[7]};
        float4 Cv = {R[8],
                     primpos[k * 3 + 0] / VOLR,
                     primpos[k * 3 + 1] / VOLR,
                     primpos[k * 3 + 2] / VOLR};
        float4 Dv = {primscale[k * 3 + 0],
                     primscale[k * 3 + 1],
                     primscale[k * 3 + 2], 0.f};
        g_prim[k * 4 + 0] = A;
        g_prim[k * 4 + 1] = Bv;
        g_prim[k * 4 + 2] = Cv;
        g_prim[k * 4 + 3] = Dv;
    }
}

// Full per-point evaluation: transform + inside test + paired fp16 trilinear gather.
__device__ __forceinline__ void eval_prim(
    const float4 A, const float4 B, const float4 C, const float4 D, int k,
    float px, float py, float pz, float s[4])
{
    float rx = px - C.y, ry = py - C.z, rz = pz - C.w;
    float lx = (rx * A.x + ry * A.w + rz * B.z) * D.x;
    float ly = (rx * A.y + ry * B.x + rz * B.w) * D.y;
    float lz = (rx * A.z + ry * B.y + rz * C.x) * D.z;
    if (!(fabsf(lx) < 1.0f && fabsf(ly) < 1.0f && fabsf(lz) < 1.0f)) return;

    float gx = fminf((lx + 1.0f) * 7.5f, 14.99999f);
    float gy = fminf((ly + 1.0f) * 7.5f, 14.99999f);
    float gz = fminf((lz + 1.0f) * 7.5f, 14.99999f);
    int x0 = (int)gx;
    int y0 = (int)gy;
    int z0 = (int)gz;
    float fx = gx - (float)x0;
    float fy = gy - (float)y0;
    float fz = gz - (float)z0;

    // 4 aligned LDG.128: each holds corners (x0, x0+1) for one (z,y)
    const uint4* T = g_tmpl + (((k * MV + z0) * MV + y0) * MV + x0);
    uint4 q00 = __ldg(T + 0);    // z0,   y0
    uint4 q01 = __ldg(T + 16);   // z0,   y0+1
    uint4 q10 = __ldg(T + 256);  // z0+1, y0
    uint4 q11 = __ldg(T + 272);  // z0+1, y0+1

    float wz0 = 1.0f - fz, wy0 = 1.0f - fy, wx0 = 1.0f - fx;
    float w000 = wz0 * wy0 * wx0, w001 = wz0 * wy0 * fx;
    float w010 = wz0 * fy * wx0,  w011 = wz0 * fy * fx;
    float w100 = fz * wy0 * wx0,  w101 = fz * wy0 * fx;
    float w110 = fz * fy * wx0,   w111 = fz * fy * fx;

#define ACC2(q, wA, wB)                                                   \
    {                                                                     \
        float2 rgA = __half22float2(*reinterpret_cast<const __half2*>(&(q).x)); \
        float2 baA = __half22float2(*reinterpret_cast<const __half2*>(&(q).y)); \
        float2 rgB = __half22float2(*reinterpret_cast<const __half2*>(&(q).z)); \
        float2 baB = __half22float2(*reinterpret_cast<const __half2*>(&(q).w)); \
        s[0] = fmaf(rgA.x, (wA), s[0]); s[1] = fmaf(rgA.y, (wA), s[1]);   \
        s[2] = fmaf(baA.x, (wA), s[2]); s[3] = fmaf(baA.y, (wA), s[3]);   \
        s[0] = fmaf(rgB.x, (wB), s[0]); s[1] = fmaf(rgB.y, (wB), s[1]);   \
        s[2] = fmaf(baB.x, (wB), s[2]); s[3] = fmaf(baB.y, (wB), s[3]);   \
    }
    ACC2(q00, w000, w001)
    ACC2(q01, w010, w011)
    ACC2(q10, w100, w101)
    ACC2(q11, w110, w111)
#undef ACC2
}

// Exact OBB slab test (cull only). Reads the GLOBAL copy (lane-divergent index;
// constant port would serialize 32-way here).
__device__ __forceinline__ bool obb_test(
    int k,
    float ox, float oy, float oz,
    float dx, float dy, float dz,
    float tmin, float tmax)
{
    float4 A = __ldg(g_prim + k * 4 + 0);
    float4 B = __ldg(g_prim + k * 4 + 1);
    float4 C = __ldg(g_prim + k * 4 + 2);
    float4 D = __ldg(g_prim + k * 4 + 3);
    float rx = ox - C.y, ry = oy - C.z, rz = oz - C.w;
    float lo3[3], ld3[3];
    lo3[0] = (rx * A.x + ry * A.w + rz * B.z) * D.x;
    lo3[1] = (rx * A.y + ry * B.x + rz * B.w) * D.y;
    lo3[2] = (rx * A.z + ry * B.y + rz * C.x) * D.z;
    ld3[0] = (dx * A.x + dy * A.w + dz * B.z) * D.x;
    ld3[1] = (dx * A.y + dy * B.x + dz * B.w) * D.y;
    ld3[2] = (dx * A.z + dy * B.y + dz * C.x) * D.z;
    float t0 = tmin, t1 = tmax;
#pragma unroll
    for (int a = 0; a < 3; a++) {
        float lo = lo3[a], ld = ld3[a];
        if (fabsf(ld) > 1e-12f) {
            float inv = 1.0f / ld;
            float ta = (-1.0f - lo) * inv;
            float tb = ( 1.0f - lo) * inv;
            t0 = fmaxf(t0, fminf(ta, tb));
            t1 = fminf(t1, fmaxf(ta, tb));
        } else if (fabsf(lo) >= 1.0f) {
            return false;
        }
    }
    return t0 <= t1;
}

// One warp per ray; lane owns steps {lane, lane+32}. 8 consecutive rays per block.
// No shared memory: prim params come from the constant port in the hot loop.
__global__ __launch_bounds__(256) void march_kernel(
    const float* __restrict__ raypos,
    const float* __restrict__ raydir,
    const float* __restrict__ tminmax,
    float* __restrict__ out)
{
    int lane = threadIdx.x & 31;
    int warpId = threadIdx.x >> 5;
    int r = blockIdx.x * 8 + warpId;  // consecutive rays (L1 template locality)

    float ox = raypos[r * 3 + 0], oy = raypos[r * 3 + 1], oz = raypos[r * 3 + 2];
    float dx = raydir[r * 3 + 0], dy = raydir[r * 3 + 1], dz = raydir[r * 3 + 2];
    float tmin = tminmax[r * 2 + 0], tmax = tminmax[r * 2 + 1];

    // Cooperative exact-OBB cull: lane tests prims {lane, lane+32}
    bool a0 = obb_test(lane,      ox, oy, oz, dx, dy, dz, tmin, tmax);
    bool a1 = obb_test(lane + 32, ox, oy, oz, dx, dy, dz, tmin, tmax);
    unsigned m0 = __ballot_sync(0xFFFFFFFFu, a0);
    unsigned m1 = __ballot_sync(0xFFFFFFFFu, a1);
    unsigned long long mask = (unsigned long long)m0 |
                              ((unsigned long long)m1 << 32);

    // Two sample points per lane: steps lane and lane+32
    float t0 = fmaf((float)lane + 0.5f,  DTST, tmin);
    float t1 = fmaf((float)lane + 32.5f, DTST, tmin);
    float p0x = fmaf(t0, dx, ox), p0y = fmaf(t0, dy, oy), p0z = fmaf(t0, dz, oz);
    float p1x = fmaf(t1, dx, ox), p1y = fmaf(t1, dy, oy), p1z = fmaf(t1, dz, oz);

    float s0[4] = {0.f, 0.f, 0.f, 0.f};
    float s1[4] = {0.f, 0.f, 0.f, 0.f};

    while (mask) {
        int k = __ffsll(mask) - 1;   // warp-uniform
        mask &= mask - 1;
        float4 A = c_prim[k * 4 + 0];   // LDC, constant port (off L1)
        float4 B = c_prim[k * 4 + 1];
        float4 C = c_prim[k * 4 + 2];
        float4 D = c_prim[k * 4 + 3];
        eval_prim(A, B, C, D, k, p0x, p0y, p0z, s0);
        eval_prim(A, B, C, D, k, p1x, p1y, p1z, s1);
    }

    // Alpha compositing via prefix sum: alpha_i = min(1, sum_{j<=i} d_j)
    float d0 = (t0 < tmax) ? s0[3] * DTST : 0.f;
    float d1 = (t1 < tmax) ? s1[3] * DTST : 0.f;

    float c0 = d0;
#pragma unroll
    for (int off = 1; off < 32; off <<= 1) {
        float v = __shfl_up_sync(0xFFFFFFFFu, c0, off);
        if (lane >= off) c0 += v;
    }
    float tot0 = __shfl_sync(0xFFFFFFFFu, c0, 31);
    float c1 = d1;
#pragma unroll
    for (int off = 1; off < 32; off <<= 1) {
        float v = __shfl_up_sync(0xFFFFFFFFu, c1, off);
        if (lane >= off) c1 += v;
    }
    float S0 = c0;            // inclusive prefix at step lane
    float S1 = tot0 + c1;     // inclusive prefix at step lane+32
    float contrib0 = fminf(1.f, S0) - fminf(1.f, S0 - d0);
    float contrib1 = fminf(1.f, S1) - fminf(1.f, S1 - d1);

    float rgbx = s0[0] * contrib0 + s1[0] * contrib1;
    float rgby = s0[1] * contrib0 + s1[1] * contrib1;
    float rgbz = s0[2] * contrib0 + s1[2] * contrib1;

#pragma unroll
    for (int off = 16; off > 0; off >>= 1) {
        rgbx += __shfl_xor_sync(0xFFFFFFFFu, rgbx, off);
        rgby += __shfl_xor_sync(0xFFFFFFFFu, rgby, off);
        rgbz += __shfl_xor_sync(0xFFFFFFFFu, rgbz, off);
    }
    float alphaF = fminf(1.f, __shfl_sync(0xFFFFFFFFu, S1, 31));

    if (lane == 0) {
        const int HWsz = HH * WW;
        out[0 * HWsz + r] = rgbx;
        out[1 * HWsz + r] = rgby;
        out[2 * HWsz + r] = rgbz;
        out[3 * HWsz + r] = alphaF;
        out[4 * HWsz + r] = rgbx;
        out[5 * HWsz + r] = rgby;
        out[6 * HWsz + r] = rgbz;
        out[7 * HWsz + r] = alphaF;
    }
}

extern "C" void kernel_launch(void* const* d_in, const int* in_sizes, int n_in,
                              void* d_out, int out_size) {
    const float* raypos    = (const float*)d_in[0];
    const float* raydir    = (const float*)d_in[1];
    const float* tminmax   = (const float*)d_in[2];
    const float* primpos   = (const float*)d_in[3];
    const float* primrot   = (const float*)d_in[4];
    const float* primscale = (const float*)d_in[5];
    const float* primrgba  = (const float*)d_in[6];
    float* out = (float*)d_out;

    pack_prep_kernel<<<1025, 256>>>(primrgba, primpos, primrot, primscale);

    // Mirror prim params into constant memory (graph-capturable D2D copy).
    void* gp = nullptr;
    cudaGetSymbolAddress(&gp, g_prim);
    cudaMemcpyToSymbolAsync(c_prim, gp, sizeof(float4) * KK * 4, 0,
                            cudaMemcpyDeviceToDevice, 0);

    march_kernel<<<HH * WW / 8, 256>>>(raypos, raydir, tminmax, out);
}

// round 12
// speedup vs baseline: 2.0224x; 1.2333x over previous
#include <cuda_runtime.h>
#include <cuda_fp16.h>

#define HH 256
#define WW 256
#define KK 64
#define MV 16
#define NSTEPS 64
#define VOLR 256.0f
#define DTST (1.0f/256.0f)

// Template with paired x-cells: entry [k][z][y][x] holds {cell(x), cell(x+1)} as
// uint4 { half2(r,g)@x, half2(b,a)@x, half2(r,g)@x+1, half2(b,a)@x+1 } : 4 MB
__device__ uint4 g_tmpl[KK * MV * MV * MV];
// Per-prim params as 4 float4 per prim:
//  A = {R00,R01,R02,R10}, B = {R11,R12,R20,R21}, C = {R22,px,py,pz}, D = {sx,sy,sz,0}
__device__ float4 g_prim[KK * 4];
// Constant-memory mirror — inner loop reads warp-uniform -> LDC (off the L1 pipe).
__constant__ float4 c_prim[KK * 4];

// Blocks 0..1023: repack template to paired fp16. Block 1024: prep prim params.
__global__ void pack_prep_kernel(const float* __restrict__ primrgba,
                                 const float* __restrict__ primpos,
                                 const float* __restrict__ primrot,
                                 const float* __restrict__ primscale) {
    int b = blockIdx.x;
    if (b < 1024) {
        int idx = b * 256 + threadIdx.x;
        int k = idx >> 12;
        int v = idx & 4095;          // z*256 + y*16 + x
        int x = v & 15;
        int v1 = (x < 15) ? v + 1 : v;  // clamp (x=15 entry never read with x1 offset)
        const float* base = primrgba + (size_t)k * 4 * 4096;
        __half2 rg0 = __floats2half2_rn(base[v], base[4096 + v]);
        __half2 ba0 = __floats2half2_rn(base[8192 + v], base[12288 + v]);
        __half2 rg1 = __floats2half2_rn(base[v1], base[4096 + v1]);
        __half2 ba1 = __floats2half2_rn(base[8192 + v1], base[12288 + v1]);
        uint4 val;
        val.x = *reinterpret_cast<unsigned*>(&rg0);
        val.y = *reinterpret_cast<unsigned*>(&ba0);
        val.z = *reinterpret_cast<unsigned*>(&rg1);
        val.w = *reinterpret_cast<unsigned*>(&ba1);
        g_tmpl[idx] = val;
    } else {
        int k = threadIdx.x;
        if (k >= KK) return;
        float R[9];
#pragma unroll
        for (int i = 0; i < 9; i++) R[i] = primrot[k * 9 + i];
        float4 A = {R[0], R[1], R[2], R[3]};
        float4 Bv = {R[4], R[5], R[6], R[7]};
        float4 Cv = {R[8],
                     primpos[k * 3 + 0] / VOLR,
                     primpos[k * 3 + 1] / VOLR,
                     primpos[k * 3 + 2] / VOLR};
        float4 Dv = {primscale[k * 3 + 0],
                     primscale[k * 3 + 1],
                     primscale[k * 3 + 2], 0.f};
        g_prim[k * 4 + 0] = A;
        g_prim[k * 4 + 1] = Bv;
        g_prim[k * 4 + 2] = Cv;
        g_prim[k * 4 + 3] = Dv;
    }
}

// Full per-point evaluation: transform + inside test + paired fp16 trilinear gather.
__device__ __forceinline__ void eval_prim(
    const float4 A, const float4 B, const float4 C, const float4 D, int k,
    float px, float py, float pz, float s[4])
{
    float rx = px - C.y, ry = py - C.z, rz = pz - C.w;
    float lx = (rx * A.x + ry * A.w + rz * B.z) * D.x;
    float ly = (rx * A.y + ry * B.x + rz * B.w) * D.y;
    float lz = (rx * A.z + ry * B.y + rz * C.x) * D.z;
    if (!(fabsf(lx) < 1.0f && fabsf(ly) < 1.0f && fabsf(lz) < 1.0f)) return;

    float gx = fminf((lx + 1.0f) * 7.5f, 14.99999f);
    float gy = fminf((ly + 1.0f) * 7.5f, 14.99999f);
    float gz = fminf((lz + 1.0f) * 7.5f, 14.99999f);
    int x0 = (int)gx;
    int y0 = (int)gy;
    int z0 = (int)gz;
    float fx = gx - (float)x0;
    float fy = gy - (float)y0;
    float fz = gz - (float)z0;

    // 4 aligned LDG.128: each holds corners (x0, x0+1) for one (z,y)
    const uint4* T = g_tmpl + (((k * MV + z0) * MV + y0) * MV + x0);
    uint4 q00 = __ldg(T + 0);    // z0,   y0
    uint4 q01 = __ldg(T + 16);   // z0,   y0+1
    uint4 q10 = __ldg(T + 256);  // z0+1, y0
    uint4 q11 = __ldg(T + 272);  // z0+1, y0+1

    float wz0 = 1.0f - fz, wy0 = 1.0f - fy, wx0 = 1.0f - fx;
    float w000 = wz0 * wy0 * wx0, w001 = wz0 * wy0 * fx;
    float w010 = wz0 * fy * wx0,  w011 = wz0 * fy * fx;
    float w100 = fz * wy0 * wx0,  w101 = fz * wy0 * fx;
    float w110 = fz * fy * wx0,   w111 = fz * fy * fx;

#define ACC2(q, wA, wB)                                                   \
    {                                                                     \
        float2 rgA = __half22float2(*reinterpret_cast<const __half2*>(&(q).x)); \
        float2 baA = __half22float2(*reinterpret_cast<const __half2*>(&(q).y)); \
        float2 rgB = __half22float2(*reinterpret_cast<const __half2*>(&(q).z)); \
        float2 baB = __half22float2(*reinterpret_cast<const __half2*>(&(q).w)); \
        s[0] = fmaf(rgA.x, (wA), s[0]); s[1] = fmaf(rgA.y, (wA), s[1]);   \
        s[2] = fmaf(baA.x, (wA), s[2]); s[3] = fmaf(baA.y, (wA), s[3]);   \
        s[0] = fmaf(rgB.x, (wB), s[0]); s[1] = fmaf(rgB.y, (wB), s[1]);   \
        s[2] = fmaf(baB.x, (wB), s[2]); s[3] = fmaf(baB.y, (wB), s[3]);   \
    }
    ACC2(q00, w000, w001)
    ACC2(q01, w010, w011)
    ACC2(q10, w100, w101)
    ACC2(q11, w110, w111)
#undef ACC2
}

// Exact OBB slab test (cull only). Reads the GLOBAL copy (lane-divergent index).
__device__ __forceinline__ bool obb_test(
    int k,
    float ox, float oy, float oz,
    float dx, float dy, float dz,
    float tmin, float tmax)
{
    float4 A = __ldg(g_prim + k * 4 + 0);
    float4 B = __ldg(g_prim + k * 4 + 1);
    float4 C = __ldg(g_prim + k * 4 + 2);
    float4 D = __ldg(g_prim + k * 4 + 3);
    float rx = ox - C.y, ry = oy - C.z, rz = oz - C.w;
    float lo3[3], ld3[3];
    lo3[0] = (rx * A.x + ry * A.w + rz * B.z) * D.x;
    lo3[1] = (rx * A.y + ry * B.x + rz * B.w) * D.y;
    lo3[2] = (rx * A.z + ry * B.y + rz * C.x) * D.z;
    ld3[0] = (dx * A.x + dy * A.w + dz * B.z) * D.x;
    ld3[1] = (dx * A.y + dy * B.x + dz * B.w) * D.y;
    ld3[2] = (dx * A.z + dy * B.y + dz * C.x) * D.z;
    float t0 = tmin, t1 = tmax;
#pragma unroll
    for (int a = 0; a < 3; a++) {
        float lo = lo3[a], ld = ld3[a];
        if (fabsf(ld) > 1e-12f) {
            float inv = 1.0f / ld;
            float ta = (-1.0f - lo) * inv;
            float tb = ( 1.0f - lo) * inv;
            t0 = fmaxf(t0, fminf(ta, tb));
            t1 = fminf(t1, fmaxf(ta, tb));
        } else if (fabsf(lo) >= 1.0f) {
            return false;
        }
    }
    return t0 <= t1;
}

// One warp per ray; lane owns steps {lane, lane+32}. 8 consecutive rays per block.
// Rows assigned CENTER-OUT across blockIdx: hot central rows launch first (LPT
// scheduling), cool edge rows backfill -> short tail. Intra-block locality intact.
__global__ __launch_bounds__(256) void march_kernel(
    const float* __restrict__ raypos,
    const float* __restrict__ raydir,
    const float* __restrict__ tminmax,
    float* __restrict__ out)
{
    int lane = threadIdx.x & 31;
    int warpId = threadIdx.x >> 5;

    // center-out row mapping: i -> 127,128,126,129,...
    int i = blockIdx.x >> 5;          // 0..255 (row index in launch order)
    int half = i & 1;
    int off = i >> 1;
    int row = half ? (128 + off) : (127 - off);
    int colg = blockIdx.x & 31;       // 8-ray column group
    int r = row * WW + colg * 8 + warpId;

    float ox = raypos[r * 3 + 0], oy = raypos[r * 3 + 1], oz = raypos[r * 3 + 2];
    float dx = raydir[r * 3 + 0], dy = raydir[r * 3 + 1], dz = raydir[r * 3 + 2];
    float tmin = tminmax[r * 2 + 0], tmax = tminmax[r * 2 + 1];

    // Cooperative exact-OBB cull: lane tests prims {lane, lane+32}
    bool a0 = obb_test(lane,      ox, oy, oz, dx, dy, dz, tmin, tmax);
    bool a1 = obb_test(lane + 32, ox, oy, oz, dx, dy, dz, tmin, tmax);
    unsigned m0 = __ballot_sync(0xFFFFFFFFu, a0);
    unsigned m1 = __ballot_sync(0xFFFFFFFFu, a1);
    unsigned long long mask = (unsigned long long)m0 |
                              ((unsigned long long)m1 << 32);

    // Two sample points per lane: steps lane and lane+32
    float t0 = fmaf((float)lane + 0.5f,  DTST, tmin);
    float t1 = fmaf((float)lane + 32.5f, DTST, tmin);
    float p0x = fmaf(t0, dx, ox), p0y = fmaf(t0, dy, oy), p0z = fmaf(t0, dz, oz);
    float p1x = fmaf(t1, dx, ox), p1y = fmaf(t1, dy, oy), p1z = fmaf(t1, dz, oz);

    float s0[4] = {0.f, 0.f, 0.f, 0.f};
    float s1[4] = {0.f, 0.f, 0.f, 0.f};

    while (mask) {
        int k = __ffsll(mask) - 1;   // warp-uniform
        mask &= mask - 1;
        float4 A = c_prim[k * 4 + 0];   // LDC, constant port (off L1)
        float4 B = c_prim[k * 4 + 1];
        float4 C = c_prim[k * 4 + 2];
        float4 D = c_prim[k * 4 + 3];
        eval_prim(A, B, C, D, k, p0x, p0y, p0z, s0);
        eval_prim(A, B, C, D, k, p1x, p1y, p1z, s1);
    }

    // Alpha compositing via prefix sum: alpha_i = min(1, sum_{j<=i} d_j)
    float d0 = (t0 < tmax) ? s0[3] * DTST : 0.f;
    float d1 = (t1 < tmax) ? s1[3] * DTST : 0.f;

    float c0 = d0;
#pragma unroll
    for (int off2 = 1; off2 < 32; off2 <<= 1) {
        float v = __shfl_up_sync(0xFFFFFFFFu, c0, off2);
        if (lane >= off2) c0 += v;
    }
    float tot0 = __shfl_sync(0xFFFFFFFFu, c0, 31);
    float c1 = d1;
#pragma unroll
    for (int off2 = 1; off2 < 32; off2 <<= 1) {
        float v = __shfl_up_sync(0xFFFFFFFFu, c1, off2);
        if (lane >= off2) c1 += v;
    }
    float S0 = c0;            // inclusive prefix at step lane
    float S1 = tot0 + c1;     // inclusive prefix at step lane+32
    float contrib0 = fminf(1.f, S0) - fminf(1.f, S0 - d0);
    float contrib1 = fminf(1.f, S1) - fminf(1.f, S1 - d1);

    float rgbx = s0[0] * contrib0 + s1[0] * contrib1;
    float rgby = s0[1] * contrib0 + s1[1] * contrib1;
    float rgbz = s0[2] * contrib0 + s1[2] * contrib1;

#pragma unroll
    for (int off2 = 16; off2 > 0; off2 >>= 1) {
        rgbx += __shfl_xor_sync(0xFFFFFFFFu, rgbx, off2);
        rgby += __shfl_xor_sync(0xFFFFFFFFu, rgby, off2);
        rgbz += __shfl_xor_sync(0xFFFFFFFFu, rgbz, off2);
    }
    float alphaF = fminf(1.f, __shfl_sync(0xFFFFFFFFu, S1, 31));

    if (lane == 0) {
        const int HWsz = HH * WW;
        out[0 * HWsz + r] = rgbx;
        out[1 * HWsz + r] = rgby;
        out[2 * HWsz + r] = rgbz;
        out[3 * HWsz + r] = alphaF;
        out[4 * HWsz + r] = rgbx;
        out[5 * HWsz + r] = rgby;
        out[6 * HWsz + r] = rgbz;
        out[7 * HWsz + r] = alphaF;
    }
}

extern "C" void kernel_launch(void* const* d_in, const int* in_sizes, int n_in,
                              void* d_out, int out_size) {
    const float* raypos    = (const float*)d_in[0];
    const float* raydir    = (const float*)d_in[1];
    const float* tminmax   = (const float*)d_in[2];
    const float* primpos   = (const float*)d_in[3];
    const float* primrot   = (const float*)d_in[4];
    const float* primscale = (const float*)d_in[5];
    const float* primrgba  = (const float*)d_in[6];
    float* out = (float*)d_out;

    pack_prep_kernel<<<1025, 256>>>(primrgba, primpos, primrot, primscale);

    // Mirror prim params into constant memory (graph-capturable D2D copy).
    void* gp = nullptr;
    cudaGetSymbolAddress(&gp, g_prim);
    cudaMemcpyToSymbolAsync(c_prim, gp, sizeof(float4) * KK * 4, 0,
                            cudaMemcpyDeviceToDevice, 0);

    march_kernel<<<HH * WW / 8, 256>>>(raypos, raydir, tminmax, out);
}

// round 14
// speedup vs baseline: 2.0351x; 1.0063x over previous
#include <cuda_runtime.h>
#include <cuda_fp16.h>

#define HH 256
#define WW 256
#define KK 64
#define MV 16
#define NSTEPS 64
#define VOLR 256.0f
#define DTST (1.0f/256.0f)

// Template with paired x-cells IN PERMUTED AXES: entry [k][z'][y'][x'] holds
// {cell(x'), cell(x'+1)} as uint4 of 4 half2. Per-prim axis permutation puts the
// dominant local march direction on x' (contiguous) so warp gathers share lines.
__device__ uint4 g_tmpl[KK * MV * MV * MV];
// Per-prim params (permuted to match): 4 float4 per prim:
//  A = {Rx0,Ry0,Rz0,Rx1}, B = {Ry1,Rz1,Rx2,Ry2}, C = {Rz2,px,py,pz}, D = {sx',sy',sz',0}
//  where column slot x' = original column p (dominant), y' = q, z' = r.
__device__ float4 g_prim[KK * 4];
// Constant-memory mirror — inner loop reads warp-uniform -> LDC (off the L1 pipe).
__constant__ float4 c_prim[KK * 4];

// Dominant local axis of the (uniform) march direction d=(0,0,1):
// ld_j = R[2][j] * s_j. Deterministic, computed identically in pack and prep.
__device__ __forceinline__ void perm_for_prim(
    const float* __restrict__ primrot, const float* __restrict__ primscale,
    int k, int& p, int& q, int& r)
{
    float a0 = fabsf(primrot[k * 9 + 6] * primscale[k * 3 + 0]);
    float a1 = fabsf(primrot[k * 9 + 7] * primscale[k * 3 + 1]);
    float a2 = fabsf(primrot[k * 9 + 8] * primscale[k * 3 + 2]);
    p = 0;
    float m = a0;
    if (a1 > m) { p = 1; m = a1; }
    if (a2 > m) { p = 2; }
    q = (p == 0) ? 1 : 0;
    r = (p == 2) ? 1 : 2;
}

// Blocks 0..1023: repack template to permuted paired fp16. Block 1024: prep prim params.
__global__ void pack_prep_kernel(const float* __restrict__ primrgba,
                                 const float* __restrict__ primpos,
                                 const float* __restrict__ primrot,
                                 const float* __restrict__ primscale) {
    int b = blockIdx.x;
    if (b < 1024) {
        int idx = b * 256 + threadIdx.x;
        int k = idx >> 12;
        int vp = idx & 4095;          // permuted z'*256 + y'*16 + x'
        int xp = vp & 15;
        int yp = (vp >> 4) & 15;
        int zp = vp >> 8;

        int p, q, r;
        perm_for_prim(primrot, primscale, k, p, q, r);

        int c[3];
        c[p] = xp; c[q] = yp; c[r] = zp;
        int v0 = c[2] * 256 + c[1] * 16 + c[0];
        c[p] = (xp < 15) ? xp + 1 : xp;
        int v1 = c[2] * 256 + c[1] * 16 + c[0];

        const float* base = primrgba + (size_t)k * 4 * 4096;
        __half2 rg0 = __floats2half2_rn(base[v0], base[4096 + v0]);
        __half2 ba0 = __floats2half2_rn(base[8192 + v0], base[12288 + v0]);
        __half2 rg1 = __floats2half2_rn(base[v1], base[4096 + v1]);
        __half2 ba1 = __floats2half2_rn(base[8192 + v1], base[12288 + v1]);
        uint4 val;
        val.x = *reinterpret_cast<unsigned*>(&rg0);
        val.y = *reinterpret_cast<unsigned*>(&ba0);
        val.z = *reinterpret_cast<unsigned*>(&rg1);
        val.w = *reinterpret_cast<unsigned*>(&ba1);
        g_tmpl[idx] = val;
    } else {
        int k = threadIdx.x;
        if (k >= KK) return;
        int p, q, r;
        perm_for_prim(primrot, primscale, k, p, q, r);
        // R[i][j] = primrot[k*9 + i*3 + j]; column j feeds local axis j.
        const float* Rm = primrot + k * 9;
        float4 A = {Rm[0 + p], Rm[0 + q], Rm[0 + r], Rm[3 + p]};
        float4 Bv = {Rm[3 + q], Rm[3 + r], Rm[6 + p], Rm[6 + q]};
        float4 Cv = {Rm[6 + r],
                     primpos[k * 3 + 0] / VOLR,
                     primpos[k * 3 + 1] / VOLR,
                     primpos[k * 3 + 2] / VOLR};
        float4 Dv = {primscale[k * 3 + p],
                     primscale[k * 3 + q],
                     primscale[k * 3 + r], 0.f};
        g_prim[k * 4 + 0] = A;
        g_prim[k * 4 + 1] = Bv;
        g_prim[k * 4 + 2] = Cv;
        g_prim[k * 4 + 3] = Dv;
    }
}

// Full per-point evaluation (permuted space): transform + inside test + gather.
__device__ __forceinline__ void eval_prim(
    const float4 A, const float4 B, const float4 C, const float4 D, int k,
    float px, float py, float pz, float s[4])
{
    float rx = px - C.y, ry = py - C.z, rz = pz - C.w;
    float lx = (rx * A.x + ry * A.w + rz * B.z) * D.x;
    float ly = (rx * A.y + ry * B.x + rz * B.w) * D.y;
    float lz = (rx * A.z + ry * B.y + rz * C.x) * D.z;
    if (!(fabsf(lx) < 1.0f && fabsf(ly) < 1.0f && fabsf(lz) < 1.0f)) return;

    float gx = fminf((lx + 1.0f) * 7.5f, 14.99999f);
    float gy = fminf((ly + 1.0f) * 7.5f, 14.99999f);
    float gz = fminf((lz + 1.0f) * 7.5f, 14.99999f);
    int x0 = (int)gx;
    int y0 = (int)gy;
    int z0 = (int)gz;
    float fx = gx - (float)x0;
    float fy = gy - (float)y0;
    float fz = gz - (float)z0;

    // 4 aligned LDG.128: each holds corners (x0, x0+1) for one (z,y)
    const uint4* T = g_tmpl + (((k * MV + z0) * MV + y0) * MV + x0);
    uint4 q00 = __ldg(T + 0);    // z0,   y0
    uint4 q01 = __ldg(T + 16);   // z0,   y0+1
    uint4 q10 = __ldg(T + 256);  // z0+1, y0
    uint4 q11 = __ldg(T + 272);  // z0+1, y0+1

    float wz0 = 1.0f - fz, wy0 = 1.0f - fy, wx0 = 1.0f - fx;
    float w000 = wz0 * wy0 * wx0, w001 = wz0 * wy0 * fx;
    float w010 = wz0 * fy * wx0,  w011 = wz0 * fy * fx;
    float w100 = fz * wy0 * wx0,  w101 = fz * wy0 * fx;
    float w110 = fz * fy * wx0,   w111 = fz * fy * fx;

#define ACC2(qq, wA, wB)                                                  \
    {                                                                     \
        float2 rgA = __half22float2(*reinterpret_cast<const __half2*>(&(qq).x)); \
        float2 baA = __half22float2(*reinterpret_cast<const __half2*>(&(qq).y)); \
        float2 rgB = __half22float2(*reinterpret_cast<const __half2*>(&(qq).z)); \
        float2 baB = __half22float2(*reinterpret_cast<const __half2*>(&(qq).w)); \
        s[0] = fmaf(rgA.x, (wA), s[0]); s[1] = fmaf(rgA.y, (wA), s[1]);   \
        s[2] = fmaf(baA.x, (wA), s[2]); s[3] = fmaf(baA.y, (wA), s[3]);   \
        s[0] = fmaf(rgB.x, (wB), s[0]); s[1] = fmaf(rgB.y, (wB), s[1]);   \
        s[2] = fmaf(baB.x, (wB), s[2]); s[3] = fmaf(baB.y, (wB), s[3]);   \
    }
    ACC2(q00, w000, w001)
    ACC2(q01, w010, w011)
    ACC2(q10, w100, w101)
    ACC2(q11, w110, w111)
#undef ACC2
}

// Exact OBB slab test (cull only). Reads the GLOBAL copy (lane-divergent index).
__device__ __forceinline__ bool obb_test(
    int k,
    float ox, float oy, float oz,
    float dx, float dy, float dz,
    float tmin, float tmax)
{
    float4 A = __ldg(g_prim + k * 4 + 0);
    float4 B = __ldg(g_prim + k * 4 + 1);
    float4 C = __ldg(g_prim + k * 4 + 2);
    float4 D = __ldg(g_prim + k * 4 + 3);
    float rx = ox - C.y, ry = oy - C.z, rz = oz - C.w;
    float lo3[3], ld3[3];
    lo3[0] = (rx * A.x + ry * A.w + rz * B.z) * D.x;
    lo3[1] = (rx * A.y + ry * B.x + rz * B.w) * D.y;
    lo3[2] = (rx * A.z + ry * B.y + rz * C.x) * D.z;
    ld3[0] = (dx * A.x + dy * A.w + dz * B.z) * D.x;
    ld3[1] = (dx * A.y + dy * B.x + dz * B.w) * D.y;
    ld3[2] = (dx * A.z + dy * B.y + dz * C.x) * D.z;
    float t0 = tmin, t1 = tmax;
#pragma unroll
    for (int a = 0; a < 3; a++) {
        float lo = lo3[a], ld = ld3[a];
        if (fabsf(ld) > 1e-12f) {
            float inv = 1.0f / ld;
            float ta = (-1.0f - lo) * inv;
            float tb = ( 1.0f - lo) * inv;
            t0 = fmaxf(t0, fminf(ta, tb));
            t1 = fminf(t1, fmaxf(ta, tb));
        } else if (fabsf(lo) >= 1.0f) {
            return false;
        }
    }
    return t0 <= t1;
}

// One warp per ray; lane owns steps {lane, lane+32}. 8 consecutive rays per block.
// Rows AND column groups assigned center-out (LPT): hot central blocks launch first.
__global__ __launch_bounds__(256) void march_kernel(
    const float* __restrict__ raypos,
    const float* __restrict__ raydir,
    const float* __restrict__ tminmax,
    float* __restrict__ out)
{
    int lane = threadIdx.x & 31;
    int warpId = threadIdx.x >> 5;

    // center-out row mapping: i -> 127,128,126,129,...
    int i = blockIdx.x >> 5;          // 0..255
    int rh = i & 1;
    int roff = i >> 1;
    int row = rh ? (128 + roff) : (127 - roff);
    // center-out column-group mapping: j -> 15,16,14,17,...
    int j = blockIdx.x & 31;
    int ch = j & 1;
    int coff = j >> 1;
    int colg = ch ? (16 + coff) : (15 - coff);
    int r = row * WW + colg * 8 + warpId;

    float ox = raypos[r * 3 + 0], oy = raypos[r * 3 + 1], oz = raypos[r * 3 + 2];
    float dx = raydir[r * 3 + 0], dy = raydir[r * 3 + 1], dz = raydir[r * 3 + 2];
    float tmin = tminmax[r * 2 + 0], tmax = tminmax[r * 2 + 1];

    // Cooperative exact-OBB cull: lane tests prims {lane, lane+32}
    bool a0 = obb_test(lane,      ox, oy, oz, dx, dy, dz, tmin, tmax);
    bool a1 = obb_test(lane + 32, ox, oy, oz, dx, dy, dz, tmin, tmax);
    unsigned m0 = __ballot_sync(0xFFFFFFFFu, a0);
    unsigned m1 = __ballot_sync(0xFFFFFFFFu, a1);
    unsigned long long mask = (unsigned long long)m0 |
                              ((unsigned long long)m1 << 32);

    // Two sample points per lane: steps lane and lane+32
    float t0 = fmaf((float)lane + 0.5f,  DTST, tmin);
    float t1 = fmaf((float)lane + 32.5f, DTST, tmin);
    float p0x = fmaf(t0, dx, ox), p0y = fmaf(t0, dy, oy), p0z = fmaf(t0, dz, oz);
    float p1x = fmaf(t1, dx, ox), p1y = fmaf(t1, dy, oy), p1z = fmaf(t1, dz, oz);

    float s0[4] = {0.f, 0.f, 0.f, 0.f};
    float s1[4] = {0.f, 0.f, 0.f, 0.f};

    while (mask) {
        int k = __ffsll(mask) - 1;   // warp-uniform
        mask &= mask - 1;
        float4 A = c_prim[k * 4 + 0];   // LDC, constant port (off L1)
        float4 B = c_prim[k * 4 + 1];
        float4 C = c_prim[k * 4 + 2];
        float4 D = c_prim[k * 4 + 3];
        eval_prim(A, B, C, D, k, p0x, p0y, p0z, s0);
        eval_prim(A, B, C, D, k, p1x, p1y, p1z, s1);
    }

    // Alpha compositing via prefix sum: alpha_i = min(1, sum_{j<=i} d_j)
    float d0 = (t0 < tmax) ? s0[3] * DTST : 0.f;
    float d1 = (t1 < tmax) ? s1[3] * DTST : 0.f;

    float c0 = d0;
#pragma unroll
    for (int off2 = 1; off2 < 32; off2 <<= 1) {
        float v = __shfl_up_sync(0xFFFFFFFFu, c0, off2);
        if (lane >= off2) c0 += v;
    }
    float tot0 = __shfl_sync(0xFFFFFFFFu, c0, 31);
    float c1 = d1;
#pragma unroll
    for (int off2 = 1; off2 < 32; off2 <<= 1) {
        float v = __shfl_up_sync(0xFFFFFFFFu, c1, off2);
        if (lane >= off2) c1 += v;
    }
    float S0 = c0;            // inclusive prefix at step lane
    float S1 = tot0 + c1;     // inclusive prefix at step lane+32
    float contrib0 = fminf(1.f, S0) - fminf(1.f, S0 - d0);
    float contrib1 = fminf(1.f, S1) - fminf(1.f, S1 - d1);

    float rgbx = s0[0] * contrib0 + s1[0] * contrib1;
    float rgby = s0[1] * contrib0 + s1[1] * contrib1;
    float rgbz = s0[2] * contrib0 + s1[2] * contrib1;

#pragma unroll
    for (int off2 = 16; off2 > 0; off2 >>= 1) {
        rgbx += __shfl_xor_sync(0xFFFFFFFFu, rgbx, off2);
        rgby += __shfl_xor_sync(0xFFFFFFFFu, rgby, off2);
        rgbz += __shfl_xor_sync(0xFFFFFFFFu, rgbz, off2);
    }
    float alphaF = fminf(1.f, __shfl_sync(0xFFFFFFFFu, S1, 31));

    if (lane == 0) {
        const int HWsz = HH * WW;
        out[0 * HWsz + r] = rgbx;
        out[1 * HWsz + r] = rgby;
        out[2 * HWsz + r] = rgbz;
        out[3 * HWsz + r] = alphaF;
        out[4 * HWsz + r] = rgbx;
        out[5 * HWsz + r] = rgby;
        out[6 * HWsz + r] = rgbz;
        out[7 * HWsz + r] = alphaF;
    }
}

extern "C" void kernel_launch(void* const* d_in, const int* in_sizes, int n_in,
                              void* d_out, int out_size) {
    const float* raypos    = (const float*)d_in[0];
    const float* raydir    = (const float*)d_in[1];
    const float* tminmax   = (const float*)d_in[2];
    const float* primpos   = (const float*)d_in[3];
    const float* primrot   = (const float*)d_in[4];
    const float* primscale = (const float*)d_in[5];
    const float* primrgba  = (const float*)d_in[6];
    float* out = (float*)d_out;

    pack_prep_kernel<<<1025, 256>>>(primrgba, primpos, primrot, primscale);

    // Mirror prim params into constant memory (graph-capturable D2D copy).
    void* gp = nullptr;
    cudaGetSymbolAddress(&gp, g_prim);
    cudaMemcpyToSymbolAsync(c_prim, gp, sizeof(float4) * KK * 4, 0,
                            cudaMemcpyDeviceToDevice, 0);

    march_kernel<<<HH * WW / 8, 256>>>(raypos, raydir, tminmax, out);
}